// round 1
// baseline (speedup 1.0000x reference)
#include <cuda_runtime.h>

// Problem constants
#define BB   2
#define SS   4096
#define DIMX 768
#define GG   256
#define HH   4
#define DKK  64
#define QSCALE 0.125f   // 1/sqrt(64)

// ---------------- scratch (device globals; no allocation allowed) ----------------
__device__ float g_q  [BB * SS * GG];                 // 8 MB, pre-scaled by QSCALE, layout [b*S+i][h*64+d]
__device__ float g_k  [BB * SS * GG];                 // 8 MB
__device__ float g_v  [BB * SS * GG];                 // 8 MB (scaled in-place by 1/Z[j] before pass2)
__device__ float g_ctx[BB * SS * GG];                 // 8 MB attention output
__device__ float g_Z  [BB * HH * SS];                 // column sums
__device__ float g_P  [(size_t)BB * HH * SS * SS];    // 512 MB: exp(scores), layout [bh][i][j]

// ---------------- small utility kernels ----------------
__global__ void zero_z_kernel() {
    int i = blockIdx.x * 256 + threadIdx.x;
    if (i < BB * HH * SS) g_Z[i] = 0.0f;
}

// v[j,h,:] *= 1/Z[b,h,j]  (one thread per (row, h), scales 64 contiguous floats)
__global__ void vz_kernel() {
    int idx = blockIdx.x * 256 + threadIdx.x;
    if (idx >= BB * SS * HH) return;
    int h   = idx & 3;
    int row = idx >> 2;             // b*S + j
    int b   = row >> 12;
    int j   = row & (SS - 1);
    float rz = 1.0f / g_Z[(size_t)(b * HH + h) * SS + j];
    float4* p = (float4*)(g_v + (size_t)row * GG + h * DKK);
#pragma unroll
    for (int q = 0; q < 16; q++) {
        float4 v = p[q];
        v.x *= rz; v.y *= rz; v.z *= rz; v.w *= rz;
        p[q] = v;
    }
}

// ---------------- shared GEMM tile: C[m0:m0+128, n0:n0+64] = A @ W^T + bias ----------------
// A: [Mrows x K=256] with leading dim lda (row-major), W: [256 x 256] row-major (out,in)
// C: row-major ld 256. Optional scale applied after bias.
__device__ __forceinline__ void gemm_tile(const float* __restrict__ A, int lda,
                                          const float* __restrict__ W,
                                          const float* __restrict__ bias,
                                          float* __restrict__ C, float scale,
                                          int m0, int n0) {
    __shared__ float As[16][136];
    __shared__ float Bs[16][68];
    int t  = threadIdx.x;
    int ty = t >> 4;          // 0..15 -> 8 rows each
    int tx = t & 15;          // 0..15 -> 4 cols each
    float acc[8][4];
#pragma unroll
    for (int i = 0; i < 8; i++)
#pragma unroll
        for (int j = 0; j < 4; j++) acc[i][j] = 0.0f;

    for (int kt = 0; kt < 256; kt += 16) {
        // load A tile 128x16, store transposed As[k][m]
#pragma unroll
        for (int it = 0; it < 2; it++) {
            int lin = it * 256 + t;
            int r   = lin >> 2;
            int c4  = (lin & 3) * 4;
            float4 v = *(const float4*)(A + (size_t)(m0 + r) * lda + kt + c4);
            As[c4 + 0][r] = v.x; As[c4 + 1][r] = v.y;
            As[c4 + 2][r] = v.z; As[c4 + 3][r] = v.w;
        }
        // load W tile: Bs[k][n] = W[(n0+n)*256 + kt + k], 64 x 16
        {
            int rn = t >> 2;
            int c4 = (t & 3) * 4;
            float4 v = *(const float4*)(W + (size_t)(n0 + rn) * 256 + kt + c4);
            Bs[c4 + 0][rn] = v.x; Bs[c4 + 1][rn] = v.y;
            Bs[c4 + 2][rn] = v.z; Bs[c4 + 3][rn] = v.w;
        }
        __syncthreads();
#pragma unroll
        for (int k = 0; k < 16; k++) {
            float a[8], bf[4];
#pragma unroll
            for (int i = 0; i < 8; i++) a[i] = As[k][ty * 8 + i];
#pragma unroll
            for (int j = 0; j < 4; j++) bf[j] = Bs[k][tx * 4 + j];
#pragma unroll
            for (int i = 0; i < 8; i++)
#pragma unroll
                for (int j = 0; j < 4; j++) acc[i][j] += a[i] * bf[j];
        }
        __syncthreads();
    }
    float bb[4];
#pragma unroll
    for (int j = 0; j < 4; j++) bb[j] = bias[n0 + tx * 4 + j];
#pragma unroll
    for (int i = 0; i < 8; i++) {
        int row = m0 + ty * 8 + i;
        float4 o;
        o.x = (acc[i][0] + bb[0]) * scale;
        o.y = (acc[i][1] + bb[1]) * scale;
        o.z = (acc[i][2] + bb[2]) * scale;
        o.w = (acc[i][3] + bb[3]) * scale;
        *(float4*)(C + (size_t)row * 256 + n0 + tx * 4) = o;
    }
}

// QKV projections: grid (M/128, 256/64, 3). q is pre-scaled by QSCALE.
__global__ void __launch_bounds__(256) qkv_kernel(
    const float* __restrict__ x,
    const float* __restrict__ wq, const float* __restrict__ bq,
    const float* __restrict__ wk, const float* __restrict__ bk,
    const float* __restrict__ wv, const float* __restrict__ bv) {
    int z = blockIdx.z;
    const float* W    = (z == 0) ? wq : (z == 1) ? wk : wv;
    const float* bias = (z == 0) ? bq : (z == 1) ? bk : bv;
    float* C          = (z == 0) ? g_q : (z == 1) ? g_k : g_v;
    float scale       = (z == 0) ? QSCALE : 1.0f;
    gemm_tile(x + z * GG, DIMX, W, bias, C, scale, blockIdx.x * 128, blockIdx.y * 64);
}

// Output projection: ctx @ wo^T + bo -> d_out
__global__ void __launch_bounds__(256) oproj_kernel(
    const float* __restrict__ wo, const float* __restrict__ bo, float* __restrict__ out) {
    gemm_tile(g_ctx, GG, wo, bo, out, 1.0f, blockIdx.x * 128, blockIdx.y * 64);
}

// ---------------- pass 1: P = exp(Q K^T), column sums Z ----------------
// grid: (S/128 j-tiles, S/128 i-tiles, B*H), 256 threads, 8x8 per thread
__global__ void __launch_bounds__(256) attn_pass1() {
    __shared__ float Qs[16][136];
    __shared__ float Ks[16][136];
    __shared__ float sums[16][129];
    int bh = blockIdx.z;
    int b  = bh >> 2, h = bh & 3;
    int i0 = blockIdx.y * 128, j0 = blockIdx.x * 128;
    const float* Qb = g_q + (size_t)b * SS * GG + h * DKK;
    const float* Kb = g_k + (size_t)b * SS * GG + h * DKK;
    float* Pb = g_P + (size_t)bh * SS * SS;
    int t = threadIdx.x, ty = t >> 4, tx = t & 15;
    float acc[8][8];
#pragma unroll
    for (int i = 0; i < 8; i++)
#pragma unroll
        for (int j = 0; j < 8; j++) acc[i][j] = 0.0f;

    for (int kt = 0; kt < DKK; kt += 16) {
#pragma unroll
        for (int it = 0; it < 2; it++) {
            int lin = it * 256 + t;
            int r   = lin >> 2;
            int c4  = (lin & 3) * 4;
            float4 vq = *(const float4*)(Qb + (size_t)(i0 + r) * GG + kt + c4);
            Qs[c4 + 0][r] = vq.x; Qs[c4 + 1][r] = vq.y;
            Qs[c4 + 2][r] = vq.z; Qs[c4 + 3][r] = vq.w;
            float4 vk = *(const float4*)(Kb + (size_t)(j0 + r) * GG + kt + c4);
            Ks[c4 + 0][r] = vk.x; Ks[c4 + 1][r] = vk.y;
            Ks[c4 + 2][r] = vk.z; Ks[c4 + 3][r] = vk.w;
        }
        __syncthreads();
#pragma unroll
        for (int k = 0; k < 16; k++) {
            float a[8], bf[8];
#pragma unroll
            for (int i = 0; i < 8; i++) a[i]  = Qs[k][ty * 8 + i];
#pragma unroll
            for (int j = 0; j < 8; j++) bf[j] = Ks[k][tx * 8 + j];
#pragma unroll
            for (int i = 0; i < 8; i++)
#pragma unroll
                for (int j = 0; j < 8; j++) acc[i][j] += a[i] * bf[j];
        }
        __syncthreads();
    }

    // exp + store P + per-thread column sums
    float rs[8];
#pragma unroll
    for (int j = 0; j < 8; j++) rs[j] = 0.0f;
#pragma unroll
    for (int i = 0; i < 8; i++) {
        float p[8];
#pragma unroll
        for (int j = 0; j < 8; j++) {
            p[j] = __expf(acc[i][j]);
            rs[j] += p[j];
        }
        float* dst = Pb + (size_t)(i0 + ty * 8 + i) * SS + j0 + tx * 8;
        *(float4*)(dst)     = make_float4(p[0], p[1], p[2], p[3]);
        *(float4*)(dst + 4) = make_float4(p[4], p[5], p[6], p[7]);
    }
    // reduce column sums across ty, one atomic per column
#pragma unroll
    for (int j = 0; j < 8; j++) sums[ty][tx * 8 + j] = rs[j];
    __syncthreads();
    if (t < 128) {
        float tot = 0.0f;
#pragma unroll
        for (int yy = 0; yy < 16; yy++) tot += sums[yy][t];
        atomicAdd(&g_Z[(size_t)bh * SS + j0 + t], tot);
    }
}

// ---------------- pass 2: ctx = P @ (V/Z) ----------------
// per (b,h): M=4096 (i), N=64 (d), K=4096 (j). grid (S/64, B*H), 128 threads, 8x4/thread
__global__ void __launch_bounds__(128) attn_pass2() {
    __shared__ float Ps[32][68];
    __shared__ float Vs[32][68];
    int bh = blockIdx.y;
    int b  = bh >> 2, h = bh & 3;
    int i0 = blockIdx.x * 64;
    const float* Pb = g_P + (size_t)bh * SS * SS;
    const float* Vb = g_v + (size_t)b * SS * GG + h * DKK;
    int t = threadIdx.x, ty = t >> 4, tx = t & 15;   // ty 0..7, tx 0..15
    float acc[8][4];
#pragma unroll
    for (int i = 0; i < 8; i++)
#pragma unroll
        for (int j = 0; j < 4; j++) acc[i][j] = 0.0f;

    for (int k0 = 0; k0 < SS; k0 += 32) {
        // P tile 64 x 32 -> transposed Ps[k][m]
#pragma unroll
        for (int it = 0; it < 4; it++) {
            int lin = it * 128 + t;   // 0..511
            int r   = lin >> 3;       // 0..63
            int c4  = (lin & 7) * 4;  // 0..28
            float4 v = *(const float4*)(Pb + (size_t)(i0 + r) * SS + k0 + c4);
            Ps[c4 + 0][r] = v.x; Ps[c4 + 1][r] = v.y;
            Ps[c4 + 2][r] = v.z; Ps[c4 + 3][r] = v.w;
        }
        // V tile 32 x 64 direct (Vs[k][n])
#pragma unroll
        for (int it = 0; it < 4; it++) {
            int lin = it * 128 + t;
            int r   = lin >> 4;        // 0..31
            int c4  = (lin & 15) * 4;  // 0..60
            float4 v = *(const float4*)(Vb + (size_t)(k0 + r) * GG + c4);
            *(float4*)&Vs[r][c4] = v;
        }
        __syncthreads();
#pragma unroll
        for (int k = 0; k < 32; k++) {
            float a[8], bf[4];
#pragma unroll
            for (int i = 0; i < 8; i++) a[i]  = Ps[k][ty * 8 + i];
#pragma unroll
            for (int j = 0; j < 4; j++) bf[j] = Vs[k][tx * 4 + j];
#pragma unroll
            for (int i = 0; i < 8; i++)
#pragma unroll
                for (int j = 0; j < 4; j++) acc[i][j] += a[i] * bf[j];
        }
        __syncthreads();
    }
#pragma unroll
    for (int i = 0; i < 8; i++) {
        int row = i0 + ty * 8 + i;
        float4 o = make_float4(acc[i][0], acc[i][1], acc[i][2], acc[i][3]);
        *(float4*)(g_ctx + (size_t)(b * SS + row) * GG + h * DKK + tx * 4) = o;
    }
}

// ---------------- launcher ----------------
extern "C" void kernel_launch(void* const* d_in, const int* in_sizes, int n_in,
                              void* d_out, int out_size) {
    const float* x  = (const float*)d_in[0];
    const float* wq = (const float*)d_in[1];
    const float* bq = (const float*)d_in[2];
    const float* wk = (const float*)d_in[3];
    const float* bk = (const float*)d_in[4];
    const float* wv = (const float*)d_in[5];
    const float* bv = (const float*)d_in[6];
    const float* wo = (const float*)d_in[7];
    const float* bo = (const float*)d_in[8];
    float* out = (float*)d_out;

    // 1) zero column sums
    zero_z_kernel<<<(BB * HH * SS + 255) / 256, 256>>>();

    // 2) QKV projections (q pre-scaled)
    {
        dim3 grid(BB * SS / 128, GG / 64, 3);
        qkv_kernel<<<grid, 256>>>(x, wq, bq, wk, bk, wv, bv);
    }

    // 3) P = exp(QK^T), Z column sums
    {
        dim3 grid(SS / 128, SS / 128, BB * HH);
        attn_pass1<<<grid, 256>>>();
    }

    // 4) scale V by 1/Z in-place
    vz_kernel<<<(BB * SS * HH + 255) / 256, 256>>>();

    // 5) ctx = P @ Vz
    {
        dim3 grid(SS / 64, BB * HH);
        attn_pass2<<<grid, 128>>>();
    }

    // 6) output projection
    {
        dim3 grid(BB * SS / 128, GG / 64);
        oproj_kernel<<<grid, 256>>>(wo, bo, out);
    }
}

// round 5
// speedup vs baseline: 1.0030x; 1.0030x over previous
#include <cuda_runtime.h>

// Problem constants
#define BB   2
#define SS   4096
#define DIMX 768
#define GG   256
#define HH   4
#define DKK  64
#define QSCALE 0.125f   // 1/sqrt(64)

// ---------------- scratch (device globals; no allocation allowed) ----------------
__device__ float g_q  [BB * SS * GG];                 // 8 MB, pre-scaled by QSCALE, layout [b*S+i][h*64+d]
__device__ float g_k  [BB * SS * GG];                 // 8 MB
__device__ float g_v  [BB * SS * GG];                 // 8 MB (scaled in-place by 1/Z[j] before pass2)
__device__ float g_ctx[BB * SS * GG];                 // 8 MB attention output
__device__ float g_Z  [BB * HH * SS];                 // column sums
__device__ float g_P  [(size_t)BB * HH * SS * SS];    // 512 MB: exp(scores), layout [bh][i][j]

// ---------------- small utility kernels ----------------
__global__ void zero_z_kernel() {
    int i = blockIdx.x * 256 + threadIdx.x;
    if (i < BB * HH * SS) g_Z[i] = 0.0f;
}

// v[j,h,:] *= 1/Z[b,h,j]  (one thread per (row, h), scales 64 contiguous floats)
__global__ void vz_kernel() {
    int idx = blockIdx.x * 256 + threadIdx.x;
    if (idx >= BB * SS * HH) return;
    int h   = idx & 3;
    int row = idx >> 2;             // b*S + j
    int b   = row >> 12;
    int j   = row & (SS - 1);
    float rz = 1.0f / g_Z[(size_t)(b * HH + h) * SS + j];
    float4* p = (float4*)(g_v + (size_t)row * GG + h * DKK);
#pragma unroll
    for (int q = 0; q < 16; q++) {
        float4 v = p[q];
        v.x *= rz; v.y *= rz; v.z *= rz; v.w *= rz;
        p[q] = v;
    }
}

// ---------------- shared GEMM tile: C[m0:m0+128, n0:n0+64] = A @ W^T + bias ----------------
// A: [Mrows x K=256] with leading dim lda (row-major), W: [256 x 256] row-major (out,in)
// C: row-major ld 256. Optional scale applied after bias.
__device__ __forceinline__ void gemm_tile(const float* __restrict__ A, int lda,
                                          const float* __restrict__ W,
                                          const float* __restrict__ bias,
                                          float* __restrict__ C, float scale,
                                          int m0, int n0) {
    __shared__ float As[16][136];
    __shared__ float Bs[16][68];
    int t  = threadIdx.x;
    int ty = t >> 4;          // 0..15 -> 8 rows each
    int tx = t & 15;          // 0..15 -> 4 cols each
    float acc[8][4];
#pragma unroll
    for (int i = 0; i < 8; i++)
#pragma unroll
        for (int j = 0; j < 4; j++) acc[i][j] = 0.0f;

    for (int kt = 0; kt < 256; kt += 16) {
        // load A tile 128x16, store transposed As[k][m]
#pragma unroll
        for (int it = 0; it < 2; it++) {
            int lin = it * 256 + t;
            int r   = lin >> 2;
            int c4  = (lin & 3) * 4;
            float4 v = *(const float4*)(A + (size_t)(m0 + r) * lda + kt + c4);
            As[c4 + 0][r] = v.x; As[c4 + 1][r] = v.y;
            As[c4 + 2][r] = v.z; As[c4 + 3][r] = v.w;
        }
        // load W tile: Bs[k][n] = W[(n0+n)*256 + kt + k], 64 x 16
        {
            int rn = t >> 2;
            int c4 = (t & 3) * 4;
            float4 v = *(const float4*)(W + (size_t)(n0 + rn) * 256 + kt + c4);
            Bs[c4 + 0][rn] = v.x; Bs[c4 + 1][rn] = v.y;
            Bs[c4 + 2][rn] = v.z; Bs[c4 + 3][rn] = v.w;
        }
        __syncthreads();
#pragma unroll
        for (int k = 0; k < 16; k++) {
            float a[8], bf[4];
#pragma unroll
            for (int i = 0; i < 8; i++) a[i] = As[k][ty * 8 + i];
#pragma unroll
            for (int j = 0; j < 4; j++) bf[j] = Bs[k][tx * 4 + j];
#pragma unroll
            for (int i = 0; i < 8; i++)
#pragma unroll
                for (int j = 0; j < 4; j++) acc[i][j] += a[i] * bf[j];
        }
        __syncthreads();
    }
    float bb[4];
#pragma unroll
    for (int j = 0; j < 4; j++) bb[j] = bias[n0 + tx * 4 + j];
#pragma unroll
    for (int i = 0; i < 8; i++) {
        int row = m0 + ty * 8 + i;
        float4 o;
        o.x = (acc[i][0] + bb[0]) * scale;
        o.y = (acc[i][1] + bb[1]) * scale;
        o.z = (acc[i][2] + bb[2]) * scale;
        o.w = (acc[i][3] + bb[3]) * scale;
        *(float4*)(C + (size_t)row * 256 + n0 + tx * 4) = o;
    }
}

// QKV projections: grid (M/128, 256/64, 3). q is pre-scaled by QSCALE.
__global__ void __launch_bounds__(256) qkv_kernel(
    const float* __restrict__ x,
    const float* __restrict__ wq, const float* __restrict__ bq,
    const float* __restrict__ wk, const float* __restrict__ bk,
    const float* __restrict__ wv, const float* __restrict__ bv) {
    int z = blockIdx.z;
    const float* W    = (z == 0) ? wq : (z == 1) ? wk : wv;
    const float* bias = (z == 0) ? bq : (z == 1) ? bk : bv;
    float* C          = (z == 0) ? g_q : (z == 1) ? g_k : g_v;
    float scale       = (z == 0) ? QSCALE : 1.0f;
    gemm_tile(x + z * GG, DIMX, W, bias, C, scale, blockIdx.x * 128, blockIdx.y * 64);
}

// Output projection: ctx @ wo^T + bo -> d_out
__global__ void __launch_bounds__(256) oproj_kernel(
    const float* __restrict__ wo, const float* __restrict__ bo, float* __restrict__ out) {
    gemm_tile(g_ctx, GG, wo, bo, out, 1.0f, blockIdx.x * 128, blockIdx.y * 64);
}

// ---------------- pass 1: P = exp(Q K^T), column sums Z ----------------
// grid: (S/128 j-tiles, S/128 i-tiles, B*H), 256 threads, 8x8 per thread
__global__ void __launch_bounds__(256) attn_pass1() {
    __shared__ float Qs[16][136];
    __shared__ float Ks[16][136];
    __shared__ float sums[16][129];
    int bh = blockIdx.z;
    int b  = bh >> 2, h = bh & 3;
    int i0 = blockIdx.y * 128, j0 = blockIdx.x * 128;
    const float* Qb = g_q + (size_t)b * SS * GG + h * DKK;
    const float* Kb = g_k + (size_t)b * SS * GG + h * DKK;
    float* Pb = g_P + (size_t)bh * SS * SS;
    int t = threadIdx.x, ty = t >> 4, tx = t & 15;
    float acc[8][8];
#pragma unroll
    for (int i = 0; i < 8; i++)
#pragma unroll
        for (int j = 0; j < 8; j++) acc[i][j] = 0.0f;

    for (int kt = 0; kt < DKK; kt += 16) {
#pragma unroll
        for (int it = 0; it < 2; it++) {
            int lin = it * 256 + t;
            int r   = lin >> 2;
            int c4  = (lin & 3) * 4;
            float4 vq = *(const float4*)(Qb + (size_t)(i0 + r) * GG + kt + c4);
            Qs[c4 + 0][r] = vq.x; Qs[c4 + 1][r] = vq.y;
            Qs[c4 + 2][r] = vq.z; Qs[c4 + 3][r] = vq.w;
            float4 vk = *(const float4*)(Kb + (size_t)(j0 + r) * GG + kt + c4);
            Ks[c4 + 0][r] = vk.x; Ks[c4 + 1][r] = vk.y;
            Ks[c4 + 2][r] = vk.z; Ks[c4 + 3][r] = vk.w;
        }
        __syncthreads();
#pragma unroll
        for (int k = 0; k < 16; k++) {
            float a[8], bf[8];
#pragma unroll
            for (int i = 0; i < 8; i++) a[i]  = Qs[k][ty * 8 + i];
#pragma unroll
            for (int j = 0; j < 8; j++) bf[j] = Ks[k][tx * 8 + j];
#pragma unroll
            for (int i = 0; i < 8; i++)
#pragma unroll
                for (int j = 0; j < 8; j++) acc[i][j] += a[i] * bf[j];
        }
        __syncthreads();
    }

    // exp + store P + per-thread column sums
    float rs[8];
#pragma unroll
    for (int j = 0; j < 8; j++) rs[j] = 0.0f;
#pragma unroll
    for (int i = 0; i < 8; i++) {
        float p[8];
#pragma unroll
        for (int j = 0; j < 8; j++) {
            p[j] = __expf(acc[i][j]);
            rs[j] += p[j];
        }
        float* dst = Pb + (size_t)(i0 + ty * 8 + i) * SS + j0 + tx * 8;
        *(float4*)(dst)     = make_float4(p[0], p[1], p[2], p[3]);
        *(float4*)(dst + 4) = make_float4(p[4], p[5], p[6], p[7]);
    }
    // reduce column sums across ty, one atomic per column
#pragma unroll
    for (int j = 0; j < 8; j++) sums[ty][tx * 8 + j] = rs[j];
    __syncthreads();
    if (t < 128) {
        float tot = 0.0f;
#pragma unroll
        for (int yy = 0; yy < 16; yy++) tot += sums[yy][t];
        atomicAdd(&g_Z[(size_t)bh * SS + j0 + t], tot);
    }
}

// ---------------- pass 2: ctx = P @ (V/Z) ----------------
// per (b,h): M=4096 (i), N=64 (d), K=4096 (j). grid (S/64, B*H), 128 threads, 8x4/thread
__global__ void __launch_bounds__(128) attn_pass2() {
    __shared__ float Ps[32][68];
    __shared__ float Vs[32][68];
    int bh = blockIdx.y;
    int b  = bh >> 2, h = bh & 3;
    int i0 = blockIdx.x * 64;
    const float* Pb = g_P + (size_t)bh * SS * SS;
    const float* Vb = g_v + (size_t)b * SS * GG + h * DKK;
    int t = threadIdx.x, ty = t >> 4, tx = t & 15;   // ty 0..7, tx 0..15
    float acc[8][4];
#pragma unroll
    for (int i = 0; i < 8; i++)
#pragma unroll
        for (int j = 0; j < 4; j++) acc[i][j] = 0.0f;

    for (int k0 = 0; k0 < SS; k0 += 32) {
        // P tile 64 x 32 -> transposed Ps[k][m]
#pragma unroll
        for (int it = 0; it < 4; it++) {
            int lin = it * 128 + t;   // 0..511
            int r   = lin >> 3;       // 0..63
            int c4  = (lin & 7) * 4;  // 0..28
            float4 v = *(const float4*)(Pb + (size_t)(i0 + r) * SS + k0 + c4);
            Ps[c4 + 0][r] = v.x; Ps[c4 + 1][r] = v.y;
            Ps[c4 + 2][r] = v.z; Ps[c4 + 3][r] = v.w;
        }
        // V tile 32 x 64 direct (Vs[k][n])
#pragma unroll
        for (int it = 0; it < 4; it++) {
            int lin = it * 128 + t;
            int r   = lin >> 4;        // 0..31
            int c4  = (lin & 15) * 4;  // 0..60
            float4 v = *(const float4*)(Vb + (size_t)(k0 + r) * GG + c4);
            *(float4*)&Vs[r][c4] = v;
        }
        __syncthreads();
#pragma unroll
        for (int k = 0; k < 32; k++) {
            float a[8], bf[4];
#pragma unroll
            for (int i = 0; i < 8; i++) a[i]  = Ps[k][ty * 8 + i];
#pragma unroll
            for (int j = 0; j < 4; j++) bf[j] = Vs[k][tx * 4 + j];
#pragma unroll
            for (int i = 0; i < 8; i++)
#pragma unroll
                for (int j = 0; j < 4; j++) acc[i][j] += a[i] * bf[j];
        }
        __syncthreads();
    }
#pragma unroll
    for (int i = 0; i < 8; i++) {
        int row = i0 + ty * 8 + i;
        float4 o = make_float4(acc[i][0], acc[i][1], acc[i][2], acc[i][3]);
        *(float4*)(g_ctx + (size_t)(b * SS + row) * GG + h * DKK + tx * 4) = o;
    }
}

// ---------------- launcher ----------------
extern "C" void kernel_launch(void* const* d_in, const int* in_sizes, int n_in,
                              void* d_out, int out_size) {
    const float* x  = (const float*)d_in[0];
    const float* wq = (const float*)d_in[1];
    const float* bq = (const float*)d_in[2];
    const float* wk = (const float*)d_in[3];
    const float* bk = (const float*)d_in[4];
    const float* wv = (const float*)d_in[5];
    const float* bv = (const float*)d_in[6];
    const float* wo = (const float*)d_in[7];
    const float* bo = (const float*)d_in[8];
    float* out = (float*)d_out;

    // 1) zero column sums
    zero_z_kernel<<<(BB * HH * SS + 255) / 256, 256>>>();

    // 2) QKV projections (q pre-scaled)
    {
        dim3 grid(BB * SS / 128, GG / 64, 3);
        qkv_kernel<<<grid, 256>>>(x, wq, bq, wk, bk, wv, bv);
    }

    // 3) P = exp(QK^T), Z column sums
    {
        dim3 grid(SS / 128, SS / 128, BB * HH);
        attn_pass1<<<grid, 256>>>();
    }

    // 4) scale V by 1/Z in-place
    vz_kernel<<<(BB * SS * HH + 255) / 256, 256>>>();

    // 5) ctx = P @ Vz
    {
        dim3 grid(SS / 64, BB * HH);
        attn_pass2<<<grid, 128>>>();
    }

    // 6) output projection
    {
        dim3 grid(BB * SS / 128, GG / 64);
        oproj_kernel<<<grid, 256>>>(wo, bo, out);
    }
}